// round 1
// baseline (speedup 1.0000x reference)
#include <cuda_runtime.h>
#include <cstdint>

#define N_MAX 100000
#define IN_C 64
#define HID_C 64
#define OUT_C 32

// ---------------- scratch (no allocations allowed) ----------------
__device__ __align__(16) float g_agg[N_MAX * IN_C];    // 25.6 MB
__device__ float g_deg[N_MAX];
__device__ __align__(16) float g_z[N_MAX * OUT_C];     // 12.8 MB
__device__ float g_as[N_MAX];
__device__ float g_ad[N_MAX];
__device__ int   g_m[N_MAX];                           // encoded segment max
__device__ float g_denom[N_MAX];
__device__ __align__(16) float g_acc[N_MAX * OUT_C];   // 12.8 MB

// order-preserving float<->int encoding for atomicMax (IEEE sign-magnitude trick)
__device__ __forceinline__ int fenc(float f) {
    int b = __float_as_int(f);
    return (b >= 0) ? b : (b ^ 0x7fffffff);
}
__device__ __forceinline__ float fdec(int k) {
    return __int_as_float((k >= 0) ? k : (k ^ 0x7fffffff));
}
__device__ __forceinline__ float lrelu(float v) {
    return v > 0.0f ? v : 0.2f * v;
}

// ---------------- K1: SAGE scatter: deg[dst]+=1, agg[dst]+=x[src] ----------------
// 16 lanes per edge, each lane one float4 (64 floats/row)
__global__ void k_sage_scatter(const float* __restrict__ x,
                               const int* __restrict__ src,
                               const int* __restrict__ dst,
                               int E) {
    unsigned t = blockIdx.x * blockDim.x + threadIdx.x;
    unsigned e = t >> 4;
    unsigned l = t & 15;
    if (e >= (unsigned)E) return;
    int s = src[e];
    int d = dst[e];
    if (l == 0) atomicAdd(&g_deg[d], 1.0f);
    float4 xv = *reinterpret_cast<const float4*>(x + (size_t)s * IN_C + l * 4);
    atomicAdd(reinterpret_cast<float4*>(g_agg + (size_t)d * IN_C) + l, xv);
}

// ---------------- K2: per-node fused forward ----------------
// one warp per node: h = relu(agg/deg @ Wl + b1 + x @ Wr); z = h @ Wg;
// a_s = z.att_src; a_d = z.att_dst; m = enc(lrelu(a_s+a_d))  (self-loop seed)
__global__ void k_node_forward(const float* __restrict__ x,
                               const float* __restrict__ W_l,
                               const float* __restrict__ W_r,
                               const float* __restrict__ b1,
                               const float* __restrict__ W_g,
                               const float* __restrict__ att_src,
                               const float* __restrict__ att_dst,
                               int n) {
    __shared__ float sWl[HID_C * IN_C];   // indexed [k*64 + j]
    __shared__ float sWr[HID_C * IN_C];
    __shared__ float sWg[HID_C * OUT_C];  // indexed [j*32 + c]
    int tid = threadIdx.x;
    for (int i = tid; i < IN_C * HID_C; i += blockDim.x) { sWl[i] = W_l[i]; sWr[i] = W_r[i]; }
    for (int i = tid; i < HID_C * OUT_C; i += blockDim.x) sWg[i] = W_g[i];
    __syncthreads();

    int node = (blockIdx.x * blockDim.x + tid) >> 5;
    int lane = tid & 31;
    if (node >= n) return;

    float inv = 1.0f / fmaxf(g_deg[node], 1.0f);
    float a0 = g_agg[(size_t)node * IN_C + lane] * inv;
    float a1 = g_agg[(size_t)node * IN_C + 32 + lane] * inv;
    float x0 = x[(size_t)node * IN_C + lane];
    float x1 = x[(size_t)node * IN_C + 32 + lane];

    float h0 = b1[lane];        // h[lane]
    float h1 = b1[32 + lane];   // h[lane+32]
#pragma unroll
    for (int k = 0; k < 32; k++) {
        float ak = __shfl_sync(0xffffffffu, a0, k);
        float xk = __shfl_sync(0xffffffffu, x0, k);
        h0 = fmaf(ak, sWl[k * 64 + lane],      fmaf(xk, sWr[k * 64 + lane],      h0));
        h1 = fmaf(ak, sWl[k * 64 + 32 + lane], fmaf(xk, sWr[k * 64 + 32 + lane], h1));
    }
#pragma unroll
    for (int k = 0; k < 32; k++) {
        float ak = __shfl_sync(0xffffffffu, a1, k);
        float xk = __shfl_sync(0xffffffffu, x1, k);
        h0 = fmaf(ak, sWl[(k + 32) * 64 + lane],      fmaf(xk, sWr[(k + 32) * 64 + lane],      h0));
        h1 = fmaf(ak, sWl[(k + 32) * 64 + 32 + lane], fmaf(xk, sWr[(k + 32) * 64 + 32 + lane], h1));
    }
    h0 = fmaxf(h0, 0.0f);
    h1 = fmaxf(h1, 0.0f);

    // z[c] for c = lane (only lanes 0..31 all valid since warp = 32)
    float z = 0.0f;
#pragma unroll
    for (int j = 0; j < 32; j++) {
        float hj = __shfl_sync(0xffffffffu, h0, j);
        z = fmaf(hj, sWg[j * OUT_C + lane], z);
    }
#pragma unroll
    for (int j = 0; j < 32; j++) {
        float hj = __shfl_sync(0xffffffffu, h1, j);
        z = fmaf(hj, sWg[(j + 32) * OUT_C + lane], z);
    }
    g_z[(size_t)node * OUT_C + lane] = z;

    float as_ = z * att_src[lane];
    float ad_ = z * att_dst[lane];
#pragma unroll
    for (int o = 16; o > 0; o >>= 1) {
        as_ += __shfl_xor_sync(0xffffffffu, as_, o);
        ad_ += __shfl_xor_sync(0xffffffffu, ad_, o);
    }
    if (lane == 0) {
        g_as[node] = as_;
        g_ad[node] = ad_;
        g_m[node] = fenc(lrelu(as_ + ad_));  // self-loop seeds the segment max
    }
}

// ---------------- K3: edge attention segment max ----------------
__global__ void k_att_max(const int* __restrict__ src,
                          const int* __restrict__ dst,
                          int E) {
    unsigned e = blockIdx.x * blockDim.x + threadIdx.x;
    if (e >= (unsigned)E) return;
    int s = src[e];
    int d = dst[e];
    float v = lrelu(g_as[s] + g_ad[d]);
    atomicMax(&g_m[d], fenc(v));
}

// ---------------- K4: edge exp + weighted scatter ----------------
// 8 lanes per edge, each lane one float4 of z[src] (32 floats/row)
__global__ void k_att_accum(const int* __restrict__ src,
                            const int* __restrict__ dst,
                            int E) {
    unsigned t = blockIdx.x * blockDim.x + threadIdx.x;
    unsigned e = t >> 3;
    unsigned l = t & 7;
    if (e >= (unsigned)E) return;
    int s = src[e];
    int d = dst[e];
    float v = lrelu(g_as[s] + g_ad[d]);
    float m = fdec(g_m[d]);
    float w = __expf(v - m);
    if (l == 0) atomicAdd(&g_denom[d], w);
    float4 zv = *reinterpret_cast<const float4*>(g_z + (size_t)s * OUT_C + l * 4);
    float4 av = make_float4(w * zv.x, w * zv.y, w * zv.z, w * zv.w);
    atomicAdd(reinterpret_cast<float4*>(g_acc + (size_t)d * OUT_C) + l, av);
}

// ---------------- K5: finalize: self-loop term, normalize, +b2, log_softmax ----------------
__global__ void k_finalize(const float* __restrict__ b2,
                           float* __restrict__ out,
                           int n) {
    int node = (blockIdx.x * blockDim.x + threadIdx.x) >> 5;
    int lane = threadIdx.x & 31;
    if (node >= n) return;

    float z = g_z[(size_t)node * OUT_C + lane];
    float e0 = lrelu(g_as[node] + g_ad[node]);
    float m = fdec(g_m[node]);
    float w0 = __expf(e0 - m);
    float num = g_acc[(size_t)node * OUT_C + lane] + w0 * z;
    float den = g_denom[node] + w0;
    float o = num / den + b2[lane];

    // log_softmax over 32 lanes
    float mx = o;
#pragma unroll
    for (int off = 16; off > 0; off >>= 1)
        mx = fmaxf(mx, __shfl_xor_sync(0xffffffffu, mx, off));
    float ex = __expf(o - mx);
    float sum = ex;
#pragma unroll
    for (int off = 16; off > 0; off >>= 1)
        sum += __shfl_xor_sync(0xffffffffu, sum, off);
    out[(size_t)node * OUT_C + lane] = o - mx - logf(sum);
}

// ---------------- launch ----------------
extern "C" void kernel_launch(void* const* d_in, const int* in_sizes, int n_in,
                              void* d_out, int out_size) {
    const float* x       = (const float*)d_in[0];
    const int*   ei      = (const int*)d_in[1];
    const float* W_l     = (const float*)d_in[2];
    const float* W_r     = (const float*)d_in[3];
    const float* b1      = (const float*)d_in[4];
    const float* W_g     = (const float*)d_in[5];
    const float* att_src = (const float*)d_in[6];
    const float* att_dst = (const float*)d_in[7];
    const float* b2      = (const float*)d_in[8];
    float* out = (float*)d_out;

    int N = in_sizes[0] / IN_C;
    int E = in_sizes[1] / 2;
    const int* src = ei;
    const int* dst = ei + E;

    // zero scratch accumulators (capturable memsets on default stream)
    void *p_agg, *p_deg, *p_den, *p_acc;
    cudaGetSymbolAddress(&p_agg, g_agg);
    cudaGetSymbolAddress(&p_deg, g_deg);
    cudaGetSymbolAddress(&p_den, g_denom);
    cudaGetSymbolAddress(&p_acc, g_acc);
    cudaMemsetAsync(p_agg, 0, (size_t)N * IN_C * sizeof(float), 0);
    cudaMemsetAsync(p_deg, 0, (size_t)N * sizeof(float), 0);
    cudaMemsetAsync(p_den, 0, (size_t)N * sizeof(float), 0);
    cudaMemsetAsync(p_acc, 0, (size_t)N * OUT_C * sizeof(float), 0);

    {
        unsigned total = (unsigned)E * 16u;
        k_sage_scatter<<<(total + 255u) / 256u, 256>>>(x, src, dst, E);
    }
    {
        int warps_per_block = 8;
        int blocks = (N + warps_per_block - 1) / warps_per_block;
        k_node_forward<<<blocks, warps_per_block * 32>>>(x, W_l, W_r, b1, W_g,
                                                         att_src, att_dst, N);
    }
    k_att_max<<<((unsigned)E + 255u) / 256u, 256>>>(src, dst, E);
    {
        unsigned total = (unsigned)E * 8u;
        k_att_accum<<<(total + 255u) / 256u, 256>>>(src, dst, E);
    }
    {
        int warps_per_block = 8;
        int blocks = (N + warps_per_block - 1) / warps_per_block;
        k_finalize<<<blocks, warps_per_block * 32>>>(b2, out, N);
    }
}

// round 2
// speedup vs baseline: 1.4318x; 1.4318x over previous
#include <cuda_runtime.h>
#include <cstdint>

#define N_MAX 100000
#define E_MAX 1600000
#define IN_C 64
#define HID_C 64
#define OUT_C 32

// ---------------- scratch (no allocations allowed) ----------------
__device__ int   g_cnt[N_MAX];        // histogram / cursor base
__device__ int   g_cur[N_MAX];        // fill cursors
__device__ int   g_off[N_MAX + 1];    // CSR offsets (by dst)
__device__ int   g_adj[E_MAX];        // src ids grouped by dst
__device__ __align__(16) float g_z[N_MAX * OUT_C];
__device__ float g_as[N_MAX];
__device__ float g_ad[N_MAX];

__device__ __forceinline__ float lrelu(float v) {
    return v > 0.0f ? v : 0.2f * v;
}

// ---------------- K1: histogram of dst ----------------
__global__ void k_hist(const int* __restrict__ dst, int E) {
    unsigned e = blockIdx.x * blockDim.x + threadIdx.x;
    if (e < (unsigned)E) atomicAdd(&g_cnt[dst[e]], 1);
}

// ---------------- K2: single-block exclusive scan (N <= 100K) ----------------
__global__ void k_scan(int n) {
    __shared__ int ssum[1024];
    int t = threadIdx.x;
    int C = (n + 1023) >> 10;
    int beg = t * C;
    int end = min(beg + C, n);
    int s = 0;
    for (int i = beg; i < end; i++) s += g_cnt[i];
    ssum[t] = s;
    __syncthreads();
#pragma unroll
    for (int off = 1; off < 1024; off <<= 1) {
        int v = (t >= off) ? ssum[t - off] : 0;
        __syncthreads();
        ssum[t] += v;
        __syncthreads();
    }
    int run = (t == 0) ? 0 : ssum[t - 1];
    for (int i = beg; i < end; i++) {
        int c = g_cnt[i];
        g_off[i] = run;
        run += c;
    }
    if (t == 1023) g_off[n] = ssum[1023];
}

// ---------------- K3: fill adjacency (src grouped by dst) ----------------
__global__ void k_fill(const int* __restrict__ src,
                       const int* __restrict__ dst,
                       int E) {
    unsigned e = blockIdx.x * blockDim.x + threadIdx.x;
    if (e >= (unsigned)E) return;
    int d = dst[e];
    int p = g_off[d] + atomicAdd(&g_cur[d], 1);
    g_adj[p] = src[e];
}

// ---------------- K4: fused SAGE gather + node forward ----------------
// one warp per node:
//   agg = mean(x[src])  (gather, no atomics)
//   h   = relu(agg @ Wl + b1 + x @ Wr)
//   z   = h @ Wg; a_s = z.att_src; a_d = z.att_dst
__global__ void k_sage_forward(const float* __restrict__ x,
                               const float* __restrict__ W_l,
                               const float* __restrict__ W_r,
                               const float* __restrict__ b1,
                               const float* __restrict__ W_g,
                               const float* __restrict__ att_src,
                               const float* __restrict__ att_dst,
                               int n) {
    __shared__ float sWl[HID_C * IN_C];
    __shared__ float sWr[HID_C * IN_C];
    __shared__ float sWg[HID_C * OUT_C];
    int tid = threadIdx.x;
    for (int i = tid; i < IN_C * HID_C; i += blockDim.x) { sWl[i] = W_l[i]; sWr[i] = W_r[i]; }
    for (int i = tid; i < HID_C * OUT_C; i += blockDim.x) sWg[i] = W_g[i];
    __syncthreads();

    int node = (blockIdx.x * blockDim.x + tid) >> 5;
    int lane = tid & 31;
    if (node >= n) return;

    int beg = g_off[node];
    int end = g_off[node + 1];

    // gather-sum of neighbor features, unrolled x4 for MLP
    float a0 = 0.0f, a1 = 0.0f;
    int j = beg;
    for (; j + 4 <= end; j += 4) {
        int s0 = g_adj[j], s1 = g_adj[j + 1], s2 = g_adj[j + 2], s3 = g_adj[j + 3];
        float v00 = x[(size_t)s0 * IN_C + lane],      v01 = x[(size_t)s0 * IN_C + 32 + lane];
        float v10 = x[(size_t)s1 * IN_C + lane],      v11 = x[(size_t)s1 * IN_C + 32 + lane];
        float v20 = x[(size_t)s2 * IN_C + lane],      v21 = x[(size_t)s2 * IN_C + 32 + lane];
        float v30 = x[(size_t)s3 * IN_C + lane],      v31 = x[(size_t)s3 * IN_C + 32 + lane];
        a0 += (v00 + v10) + (v20 + v30);
        a1 += (v01 + v11) + (v21 + v31);
    }
    for (; j < end; j++) {
        int s = g_adj[j];
        a0 += x[(size_t)s * IN_C + lane];
        a1 += x[(size_t)s * IN_C + 32 + lane];
    }
    float inv = 1.0f / fmaxf((float)(end - beg), 1.0f);
    a0 *= inv;
    a1 *= inv;

    float x0 = x[(size_t)node * IN_C + lane];
    float x1 = x[(size_t)node * IN_C + 32 + lane];

    float h0 = b1[lane];
    float h1 = b1[32 + lane];
#pragma unroll
    for (int k = 0; k < 32; k++) {
        float ak = __shfl_sync(0xffffffffu, a0, k);
        float xk = __shfl_sync(0xffffffffu, x0, k);
        h0 = fmaf(ak, sWl[k * 64 + lane],      fmaf(xk, sWr[k * 64 + lane],      h0));
        h1 = fmaf(ak, sWl[k * 64 + 32 + lane], fmaf(xk, sWr[k * 64 + 32 + lane], h1));
    }
#pragma unroll
    for (int k = 0; k < 32; k++) {
        float ak = __shfl_sync(0xffffffffu, a1, k);
        float xk = __shfl_sync(0xffffffffu, x1, k);
        h0 = fmaf(ak, sWl[(k + 32) * 64 + lane],      fmaf(xk, sWr[(k + 32) * 64 + lane],      h0));
        h1 = fmaf(ak, sWl[(k + 32) * 64 + 32 + lane], fmaf(xk, sWr[(k + 32) * 64 + 32 + lane], h1));
    }
    h0 = fmaxf(h0, 0.0f);
    h1 = fmaxf(h1, 0.0f);

    float z = 0.0f;
#pragma unroll
    for (int jj = 0; jj < 32; jj++) {
        float hj = __shfl_sync(0xffffffffu, h0, jj);
        z = fmaf(hj, sWg[jj * OUT_C + lane], z);
    }
#pragma unroll
    for (int jj = 0; jj < 32; jj++) {
        float hj = __shfl_sync(0xffffffffu, h1, jj);
        z = fmaf(hj, sWg[(jj + 32) * OUT_C + lane], z);
    }
    g_z[(size_t)node * OUT_C + lane] = z;

    float as_ = z * att_src[lane];
    float ad_ = z * att_dst[lane];
#pragma unroll
    for (int o = 16; o > 0; o >>= 1) {
        as_ += __shfl_xor_sync(0xffffffffu, as_, o);
        ad_ += __shfl_xor_sync(0xffffffffu, ad_, o);
    }
    if (lane == 0) {
        g_as[node] = as_;
        g_ad[node] = ad_;
    }
}

// ---------------- K5: fused GAT gather (max + softmax + weighted sum + log_softmax) ----------------
// one warp per dst node, no atomics
__global__ void k_gat(const float* __restrict__ b2,
                      float* __restrict__ out,
                      int n) {
    int node = (blockIdx.x * blockDim.x + threadIdx.x) >> 5;
    int lane = threadIdx.x & 31;
    if (node >= n) return;

    int beg = g_off[node];
    int end = g_off[node + 1];

    float ad_ = g_ad[node];
    float e_self = lrelu(g_as[node] + ad_);

    // pass 1: segment max (lanes partition neighbors)
    float m = e_self;
    for (int j = beg + lane; j < end; j += 32)
        m = fmaxf(m, lrelu(g_as[g_adj[j]] + ad_));
#pragma unroll
    for (int o = 16; o > 0; o >>= 1)
        m = fmaxf(m, __shfl_xor_sync(0xffffffffu, m, o));

    // pass 2: weighted accumulation, unrolled x4
    float zl = g_z[(size_t)node * OUT_C + lane];
    float w_self = __expf(e_self - m);
    float sum = w_self;
    float acc = w_self * zl;

    int j = beg;
    for (; j + 4 <= end; j += 4) {
        int s0 = g_adj[j], s1 = g_adj[j + 1], s2 = g_adj[j + 2], s3 = g_adj[j + 3];
        float w0 = __expf(lrelu(g_as[s0] + ad_) - m);
        float w1 = __expf(lrelu(g_as[s1] + ad_) - m);
        float w2 = __expf(lrelu(g_as[s2] + ad_) - m);
        float w3 = __expf(lrelu(g_as[s3] + ad_) - m);
        float z0 = g_z[(size_t)s0 * OUT_C + lane];
        float z1 = g_z[(size_t)s1 * OUT_C + lane];
        float z2 = g_z[(size_t)s2 * OUT_C + lane];
        float z3 = g_z[(size_t)s3 * OUT_C + lane];
        sum += (w0 + w1) + (w2 + w3);
        acc = fmaf(w0, z0, fmaf(w1, z1, fmaf(w2, z2, fmaf(w3, z3, acc))));
    }
    for (; j < end; j++) {
        int s = g_adj[j];
        float w = __expf(lrelu(g_as[s] + ad_) - m);
        sum += w;
        acc = fmaf(w, g_z[(size_t)s * OUT_C + lane], acc);
    }

    float o = acc / sum + b2[lane];

    // log_softmax over 32 lanes
    float mx = o;
#pragma unroll
    for (int off = 16; off > 0; off >>= 1)
        mx = fmaxf(mx, __shfl_xor_sync(0xffffffffu, mx, off));
    float ex = __expf(o - mx);
    float se = ex;
#pragma unroll
    for (int off = 16; off > 0; off >>= 1)
        se += __shfl_xor_sync(0xffffffffu, se, off);
    out[(size_t)node * OUT_C + lane] = o - mx - logf(se);
}

// ---------------- launch ----------------
extern "C" void kernel_launch(void* const* d_in, const int* in_sizes, int n_in,
                              void* d_out, int out_size) {
    const float* x       = (const float*)d_in[0];
    const int*   ei      = (const int*)d_in[1];
    const float* W_l     = (const float*)d_in[2];
    const float* W_r     = (const float*)d_in[3];
    const float* b1      = (const float*)d_in[4];
    const float* W_g     = (const float*)d_in[5];
    const float* att_src = (const float*)d_in[6];
    const float* att_dst = (const float*)d_in[7];
    const float* b2      = (const float*)d_in[8];
    float* out = (float*)d_out;

    int N = in_sizes[0] / IN_C;
    int E = in_sizes[1] / 2;
    const int* src = ei;
    const int* dst = ei + E;

    void *p_cnt, *p_cur;
    cudaGetSymbolAddress(&p_cnt, g_cnt);
    cudaGetSymbolAddress(&p_cur, g_cur);
    cudaMemsetAsync(p_cnt, 0, (size_t)N * sizeof(int), 0);
    cudaMemsetAsync(p_cur, 0, (size_t)N * sizeof(int), 0);

    k_hist<<<((unsigned)E + 255u) / 256u, 256>>>(dst, E);
    k_scan<<<1, 1024>>>(N);
    k_fill<<<((unsigned)E + 255u) / 256u, 256>>>(src, dst, E);

    {
        int warps_per_block = 8;
        int blocks = (N + warps_per_block - 1) / warps_per_block;
        k_sage_forward<<<blocks, warps_per_block * 32>>>(x, W_l, W_r, b1, W_g,
                                                         att_src, att_dst, N);
        k_gat<<<blocks, warps_per_block * 32>>>(b2, out, N);
    }
}

// round 3
// speedup vs baseline: 1.5910x; 1.1112x over previous
#include <cuda_runtime.h>
#include <cstdint>

#define N_MAX 100000
#define E_MAX 1600000
#define IN_C 64
#define HID_C 64
#define OUT_C 32
#define FULL 0xffffffffu

// ---------------- scratch (no allocations allowed) ----------------
__device__ int   g_cnt[N_MAX];
__device__ int   g_cur[N_MAX];
__device__ int   g_off[N_MAX + 1];
__device__ int   g_adj[E_MAX];
__device__ __align__(16) float g_agg[N_MAX * IN_C];   // mean-aggregated features
__device__ __align__(16) float g_z[N_MAX * OUT_C];
__device__ float g_as[N_MAX];
__device__ float g_ad[N_MAX];

__device__ __forceinline__ float lrelu(float v) {
    return v > 0.0f ? v : 0.2f * v;
}

// ---------------- K1: histogram of dst ----------------
__global__ void k_hist(const int* __restrict__ dst, int E) {
    unsigned e = blockIdx.x * blockDim.x + threadIdx.x;
    if (e < (unsigned)E) atomicAdd(&g_cnt[dst[e]], 1);
}

// ---------------- K2: single-block exclusive scan ----------------
__global__ void k_scan(int n) {
    __shared__ int ssum[1024];
    int t = threadIdx.x;
    int C = (n + 1023) >> 10;
    int beg = t * C;
    int end = min(beg + C, n);
    int s = 0;
    for (int i = beg; i < end; i++) s += g_cnt[i];
    ssum[t] = s;
    __syncthreads();
#pragma unroll
    for (int off = 1; off < 1024; off <<= 1) {
        int v = (t >= off) ? ssum[t - off] : 0;
        __syncthreads();
        ssum[t] += v;
        __syncthreads();
    }
    int run = (t == 0) ? 0 : ssum[t - 1];
    for (int i = beg; i < end; i++) {
        int c = g_cnt[i];
        g_off[i] = run;
        run += c;
    }
    if (t == 1023) g_off[n] = ssum[1023];
}

// ---------------- K3: fill adjacency (src grouped by dst) ----------------
__global__ void k_fill(const int* __restrict__ src,
                       const int* __restrict__ dst,
                       int E) {
    unsigned e = blockIdx.x * blockDim.x + threadIdx.x;
    if (e >= (unsigned)E) return;
    int d = dst[e];
    int p = g_off[d] + atomicAdd(&g_cur[d], 1);
    g_adj[p] = src[e];
}

// ---------------- K4a: mean aggregation (vectorized gather) ----------------
// one warp per node; 32 lanes = 2 neighbors x 16 float4 chunks
__global__ void k_agg(const float* __restrict__ x, int n) {
    int node = (blockIdx.x * blockDim.x + threadIdx.x) >> 5;
    int lane = threadIdx.x & 31;
    if (node >= n) return;
    int beg = g_off[node];
    int end = g_off[node + 1];
    int half = lane >> 4;   // which of 2 neighbors this lane reads
    int q = lane & 15;      // float4 chunk within 64-float row

    float4 acc0 = make_float4(0.f, 0.f, 0.f, 0.f);
    float4 acc1 = make_float4(0.f, 0.f, 0.f, 0.f);
    int j = beg;
    for (; j + 4 <= end; j += 4) {
        int s0 = g_adj[j + half];
        int s1 = g_adj[j + 2 + half];
        float4 v0 = *reinterpret_cast<const float4*>(x + (size_t)s0 * IN_C + q * 4);
        float4 v1 = *reinterpret_cast<const float4*>(x + (size_t)s1 * IN_C + q * 4);
        acc0.x += v0.x; acc0.y += v0.y; acc0.z += v0.z; acc0.w += v0.w;
        acc1.x += v1.x; acc1.y += v1.y; acc1.z += v1.z; acc1.w += v1.w;
    }
    for (; j + 2 <= end; j += 2) {
        int s = g_adj[j + half];
        float4 v = *reinterpret_cast<const float4*>(x + (size_t)s * IN_C + q * 4);
        acc0.x += v.x; acc0.y += v.y; acc0.z += v.z; acc0.w += v.w;
    }
    if (j < end && half == 0) {
        int s = g_adj[j];
        float4 v = *reinterpret_cast<const float4*>(x + (size_t)s * IN_C + q * 4);
        acc0.x += v.x; acc0.y += v.y; acc0.z += v.z; acc0.w += v.w;
    }
    acc0.x += acc1.x; acc0.y += acc1.y; acc0.z += acc1.z; acc0.w += acc1.w;
    // combine the two halves of the warp
    acc0.x += __shfl_down_sync(FULL, acc0.x, 16);
    acc0.y += __shfl_down_sync(FULL, acc0.y, 16);
    acc0.z += __shfl_down_sync(FULL, acc0.z, 16);
    acc0.w += __shfl_down_sync(FULL, acc0.w, 16);

    float inv = 1.0f / fmaxf((float)(end - beg), 1.0f);
    if (lane < 16) {
        float4 r = make_float4(acc0.x * inv, acc0.y * inv, acc0.z * inv, acc0.w * inv);
        *reinterpret_cast<float4*>(g_agg + (size_t)node * IN_C + q * 4) = r;
    }
}

// ---------------- K4b: node forward GEMM ----------------
// one warp per node: h = relu(agg@Wl + b1 + x@Wr); z = h@Wg; a_s/a_d scores
__global__ void k_forward(const float* __restrict__ x,
                          const float* __restrict__ W_l,
                          const float* __restrict__ W_r,
                          const float* __restrict__ b1,
                          const float* __restrict__ W_g,
                          const float* __restrict__ att_src,
                          const float* __restrict__ att_dst,
                          int n) {
    __shared__ float sWl[HID_C * IN_C];
    __shared__ float sWr[HID_C * IN_C];
    __shared__ float sWg[HID_C * OUT_C];
    int tid = threadIdx.x;
    for (int i = tid; i < IN_C * HID_C; i += blockDim.x) { sWl[i] = W_l[i]; sWr[i] = W_r[i]; }
    for (int i = tid; i < HID_C * OUT_C; i += blockDim.x) sWg[i] = W_g[i];
    __syncthreads();

    int node = (blockIdx.x * blockDim.x + tid) >> 5;
    int lane = tid & 31;
    if (node >= n) return;

    float a0 = g_agg[(size_t)node * IN_C + lane];
    float a1 = g_agg[(size_t)node * IN_C + 32 + lane];
    float x0 = x[(size_t)node * IN_C + lane];
    float x1 = x[(size_t)node * IN_C + 32 + lane];

    float h0 = b1[lane];
    float h1 = b1[32 + lane];
#pragma unroll
    for (int k = 0; k < 32; k++) {
        float ak = __shfl_sync(FULL, a0, k);
        float xk = __shfl_sync(FULL, x0, k);
        h0 = fmaf(ak, sWl[k * 64 + lane],      fmaf(xk, sWr[k * 64 + lane],      h0));
        h1 = fmaf(ak, sWl[k * 64 + 32 + lane], fmaf(xk, sWr[k * 64 + 32 + lane], h1));
    }
#pragma unroll
    for (int k = 0; k < 32; k++) {
        float ak = __shfl_sync(FULL, a1, k);
        float xk = __shfl_sync(FULL, x1, k);
        h0 = fmaf(ak, sWl[(k + 32) * 64 + lane],      fmaf(xk, sWr[(k + 32) * 64 + lane],      h0));
        h1 = fmaf(ak, sWl[(k + 32) * 64 + 32 + lane], fmaf(xk, sWr[(k + 32) * 64 + 32 + lane], h1));
    }
    h0 = fmaxf(h0, 0.0f);
    h1 = fmaxf(h1, 0.0f);

    float z = 0.0f;
#pragma unroll
    for (int jj = 0; jj < 32; jj++) {
        float hj = __shfl_sync(FULL, h0, jj);
        z = fmaf(hj, sWg[jj * OUT_C + lane], z);
    }
#pragma unroll
    for (int jj = 0; jj < 32; jj++) {
        float hj = __shfl_sync(FULL, h1, jj);
        z = fmaf(hj, sWg[(jj + 32) * OUT_C + lane], z);
    }
    g_z[(size_t)node * OUT_C + lane] = z;

    float as_ = z * att_src[lane];
    float ad_ = z * att_dst[lane];
#pragma unroll
    for (int o = 16; o > 0; o >>= 1) {
        as_ += __shfl_xor_sync(FULL, as_, o);
        ad_ += __shfl_xor_sync(FULL, ad_, o);
    }
    if (lane == 0) {
        g_as[node] = as_;
        g_ad[node] = ad_;
    }
}

// ---------------- K5: fused GAT (vectorized gather) ----------------
// one warp per dst node; 32 lanes = 4 neighbors x 8 float4 chunks
__global__ void k_gat(const float* __restrict__ b2,
                      float* __restrict__ out,
                      int n) {
    int node = (blockIdx.x * blockDim.x + threadIdx.x) >> 5;
    int lane = threadIdx.x & 31;
    if (node >= n) return;
    int beg = g_off[node];
    int end = g_off[node + 1];
    int grp = lane >> 3;   // neighbor sub-group 0..3
    int q = lane & 7;      // float4 chunk within 32-float row

    float ad_ = g_ad[node];
    float e_self = lrelu(g_as[node] + ad_);

    // pass 1: segment max (lanes partition neighbors)
    float m = e_self;
    for (int j = beg + lane; j < end; j += 32)
        m = fmaxf(m, lrelu(g_as[g_adj[j]] + ad_));
#pragma unroll
    for (int o = 16; o > 0; o >>= 1)
        m = fmaxf(m, __shfl_xor_sync(FULL, m, o));

    // pass 2: weighted accumulation, 4 neighbors per warp step
    float sum = 0.0f;
    float4 acc = make_float4(0.f, 0.f, 0.f, 0.f);
    if (grp == 0) {
        float w = __expf(e_self - m);
        sum = w;
        float4 zv = *reinterpret_cast<const float4*>(g_z + (size_t)node * OUT_C + q * 4);
        acc = make_float4(w * zv.x, w * zv.y, w * zv.z, w * zv.w);
    }
    for (int j = beg + grp; j < end; j += 4) {
        int s = g_adj[j];
        float w = __expf(lrelu(g_as[s] + ad_) - m);
        sum += w;
        float4 zv = *reinterpret_cast<const float4*>(g_z + (size_t)s * OUT_C + q * 4);
        acc.x = fmaf(w, zv.x, acc.x);
        acc.y = fmaf(w, zv.y, acc.y);
        acc.z = fmaf(w, zv.z, acc.z);
        acc.w = fmaf(w, zv.w, acc.w);
    }
    // reduce across the 4 neighbor groups (xor bits 3,4 — q bits unchanged)
    sum += __shfl_xor_sync(FULL, sum, 8);
    sum += __shfl_xor_sync(FULL, sum, 16);
    acc.x += __shfl_xor_sync(FULL, acc.x, 8);  acc.x += __shfl_xor_sync(FULL, acc.x, 16);
    acc.y += __shfl_xor_sync(FULL, acc.y, 8);  acc.y += __shfl_xor_sync(FULL, acc.y, 16);
    acc.z += __shfl_xor_sync(FULL, acc.z, 8);  acc.z += __shfl_xor_sync(FULL, acc.z, 16);
    acc.w += __shfl_xor_sync(FULL, acc.w, 8);  acc.w += __shfl_xor_sync(FULL, acc.w, 16);

    float inv = 1.0f / sum;
    float4 o4;
    o4.x = acc.x * inv + b2[q * 4 + 0];
    o4.y = acc.y * inv + b2[q * 4 + 1];
    o4.z = acc.z * inv + b2[q * 4 + 2];
    o4.w = acc.w * inv + b2[q * 4 + 3];

    // log_softmax over the 32 outputs (8 chunks x 4 comps, replicated per group)
    float mx = fmaxf(fmaxf(o4.x, o4.y), fmaxf(o4.z, o4.w));
#pragma unroll
    for (int off = 1; off < 8; off <<= 1)
        mx = fmaxf(mx, __shfl_xor_sync(FULL, mx, off));
    float se = __expf(o4.x - mx) + __expf(o4.y - mx) + __expf(o4.z - mx) + __expf(o4.w - mx);
#pragma unroll
    for (int off = 1; off < 8; off <<= 1)
        se += __shfl_xor_sync(FULL, se, off);
    float ls = mx + logf(se);

    if (lane < 8) {
        float4 r = make_float4(o4.x - ls, o4.y - ls, o4.z - ls, o4.w - ls);
        *reinterpret_cast<float4*>(out + (size_t)node * OUT_C + q * 4) = r;
    }
}

// ---------------- launch ----------------
extern "C" void kernel_launch(void* const* d_in, const int* in_sizes, int n_in,
                              void* d_out, int out_size) {
    const float* x       = (const float*)d_in[0];
    const int*   ei      = (const int*)d_in[1];
    const float* W_l     = (const float*)d_in[2];
    const float* W_r     = (const float*)d_in[3];
    const float* b1      = (const float*)d_in[4];
    const float* W_g     = (const float*)d_in[5];
    const float* att_src = (const float*)d_in[6];
    const float* att_dst = (const float*)d_in[7];
    const float* b2      = (const float*)d_in[8];
    float* out = (float*)d_out;

    int N = in_sizes[0] / IN_C;
    int E = in_sizes[1] / 2;
    const int* src = ei;
    const int* dst = ei + E;

    void *p_cnt, *p_cur;
    cudaGetSymbolAddress(&p_cnt, g_cnt);
    cudaGetSymbolAddress(&p_cur, g_cur);
    cudaMemsetAsync(p_cnt, 0, (size_t)N * sizeof(int), 0);
    cudaMemsetAsync(p_cur, 0, (size_t)N * sizeof(int), 0);

    k_hist<<<((unsigned)E + 255u) / 256u, 256>>>(dst, E);
    k_scan<<<1, 1024>>>(N);
    k_fill<<<((unsigned)E + 255u) / 256u, 256>>>(src, dst, E);

    k_agg<<<(N + 7) / 8, 256>>>(x, N);
    k_forward<<<(N + 15) / 16, 512>>>(x, W_l, W_r, b1, W_g, att_src, att_dst, N);
    k_gat<<<(N + 7) / 8, 256>>>(b2, out, N);
}

// round 4
// speedup vs baseline: 2.6292x; 1.6526x over previous
#include <cuda_runtime.h>
#include <cstdint>

#define N_MAX 100000
#define E_MAX 1600000
#define IN_C 64
#define HID_C 64
#define OUT_C 32
#define FULL 0xffffffffu

// ---------------- scratch (no allocations allowed) ----------------
__device__ int   g_cnt[N_MAX];
__device__ int   g_cur[N_MAX];
__device__ int   g_off[N_MAX + 1];
__device__ int   g_adj[E_MAX];
__device__ int   g_bsum[128];
__device__ int   g_bpre[128];
__device__ __align__(16) float g_agg[N_MAX * IN_C];
__device__ __align__(16) float g_z[N_MAX * OUT_C];
__device__ float g_as[N_MAX];
__device__ float g_ad[N_MAX];

__device__ __forceinline__ float lrelu(float v) {
    return v > 0.0f ? v : 0.2f * v;
}

// packed f32x2 helpers (Blackwell)
__device__ __forceinline__ void fma2(unsigned long long& d,
                                     unsigned long long a,
                                     unsigned long long b) {
    asm("fma.rn.f32x2 %0, %1, %2, %0;" : "+l"(d) : "l"(a), "l"(b));
}
__device__ __forceinline__ unsigned long long pack2(float v) {
    unsigned long long r;
    asm("mov.b64 %0, {%1, %1};" : "=l"(r) : "f"(v));
    return r;
}
__device__ __forceinline__ unsigned long long packf(float a, float b) {
    unsigned long long r;
    asm("mov.b64 %0, {%1, %2};" : "=l"(r) : "f"(a), "f"(b));
    return r;
}
__device__ __forceinline__ float2 unpack2(unsigned long long v) {
    float2 f;
    asm("mov.b64 {%0, %1}, %2;" : "=f"(f.x), "=f"(f.y) : "l"(v));
    return f;
}

// ---------------- K1: histogram of dst ----------------
__global__ void k_hist(const int* __restrict__ dst, int E) {
    unsigned e = blockIdx.x * blockDim.x + threadIdx.x;
    if (e < (unsigned)E) atomicAdd(&g_cnt[dst[e]], 1);
}

// ---------------- K2: hierarchical exclusive scan ----------------
__global__ void k_scan_local(int n) {
    __shared__ int wsum[32];
    int b = blockIdx.x, t = threadIdx.x;
    int i = b * 1024 + t;
    int v = (i < n) ? g_cnt[i] : 0;
    int orig = v;
    int lane = t & 31, w = t >> 5;
#pragma unroll
    for (int o = 1; o < 32; o <<= 1) {
        int u = __shfl_up_sync(FULL, v, o);
        if (lane >= o) v += u;
    }
    if (lane == 31) wsum[w] = v;
    __syncthreads();
    if (w == 0) {
        int s = wsum[lane];
#pragma unroll
        for (int o = 1; o < 32; o <<= 1) {
            int u = __shfl_up_sync(FULL, s, o);
            if (lane >= o) s += u;
        }
        wsum[lane] = s;
    }
    __syncthreads();
    int excl = v - orig + (w > 0 ? wsum[w - 1] : 0);
    if (i < n) g_off[i] = excl;
    if (t == 1023) g_bsum[b] = wsum[31];
}

__global__ void k_scan_bsums(int nb, int n) {
    __shared__ int tmp[128];
    int t = threadIdx.x;
    int v = (t < nb) ? g_bsum[t] : 0;
    tmp[t] = v;
    __syncthreads();
    for (int o = 1; o < 128; o <<= 1) {
        int u = (t >= o) ? tmp[t - o] : 0;
        __syncthreads();
        tmp[t] += u;
        __syncthreads();
    }
    if (t < nb) g_bpre[t] = tmp[t] - v;
    if (t == nb - 1) g_off[n] = tmp[t];
}

__global__ void k_scan_add(int n) {
    int b = blockIdx.x;
    int i = b * 1024 + threadIdx.x;
    if (i < n && b > 0) g_off[i] += g_bpre[b];
}

// ---------------- K3: fill adjacency ----------------
__global__ void k_fill(const int* __restrict__ src,
                       const int* __restrict__ dst,
                       int E) {
    unsigned e = blockIdx.x * blockDim.x + threadIdx.x;
    if (e >= (unsigned)E) return;
    int d = dst[e];
    int p = g_off[d] + atomicAdd(&g_cur[d], 1);
    g_adj[p] = src[e];
}

// ---------------- K4a: mean aggregation (vectorized gather) ----------------
__global__ void k_agg(const float* __restrict__ x, int n) {
    int node = (blockIdx.x * blockDim.x + threadIdx.x) >> 5;
    int lane = threadIdx.x & 31;
    if (node >= n) return;
    int beg = g_off[node];
    int end = g_off[node + 1];
    int half = lane >> 4;
    int q = lane & 15;

    float4 acc0 = make_float4(0.f, 0.f, 0.f, 0.f);
    float4 acc1 = make_float4(0.f, 0.f, 0.f, 0.f);
    int j = beg;
    for (; j + 4 <= end; j += 4) {
        int s0 = g_adj[j + half];
        int s1 = g_adj[j + 2 + half];
        float4 v0 = *reinterpret_cast<const float4*>(x + (size_t)s0 * IN_C + q * 4);
        float4 v1 = *reinterpret_cast<const float4*>(x + (size_t)s1 * IN_C + q * 4);
        acc0.x += v0.x; acc0.y += v0.y; acc0.z += v0.z; acc0.w += v0.w;
        acc1.x += v1.x; acc1.y += v1.y; acc1.z += v1.z; acc1.w += v1.w;
    }
    for (; j + 2 <= end; j += 2) {
        int s = g_adj[j + half];
        float4 v = *reinterpret_cast<const float4*>(x + (size_t)s * IN_C + q * 4);
        acc0.x += v.x; acc0.y += v.y; acc0.z += v.z; acc0.w += v.w;
    }
    if (j < end && half == 0) {
        int s = g_adj[j];
        float4 v = *reinterpret_cast<const float4*>(x + (size_t)s * IN_C + q * 4);
        acc0.x += v.x; acc0.y += v.y; acc0.z += v.z; acc0.w += v.w;
    }
    acc0.x += acc1.x; acc0.y += acc1.y; acc0.z += acc1.z; acc0.w += acc1.w;
    acc0.x += __shfl_down_sync(FULL, acc0.x, 16);
    acc0.y += __shfl_down_sync(FULL, acc0.y, 16);
    acc0.z += __shfl_down_sync(FULL, acc0.z, 16);
    acc0.w += __shfl_down_sync(FULL, acc0.w, 16);

    float inv = 1.0f / fmaxf((float)(end - beg), 1.0f);
    if (lane < 16) {
        float4 r = make_float4(acc0.x * inv, acc0.y * inv, acc0.z * inv, acc0.w * inv);
        *reinterpret_cast<float4*>(g_agg + (size_t)node * IN_C + q * 4) = r;
    }
}

// ---------------- K4b: register-tiled node forward GEMM ----------------
// 64-node tiles, 128 threads. K=128 ([agg|x] @ [Wl;Wr]) with packed f32x2 FMA.
// Each thread: 8 nodes (4 node-pairs) x 4 cols.
__global__ void __launch_bounds__(128) k_forward(
        const float* __restrict__ x,
        const float* __restrict__ W_l,
        const float* __restrict__ W_r,
        const float* __restrict__ b1,
        const float* __restrict__ W_g,
        const float* __restrict__ att_src,
        const float* __restrict__ att_dst,
        int n) {
    extern __shared__ float sm[];
    float* sIn = sm;                 // [128][64] (k-major); reused as sH [64][64]
    float* sW  = sm + 128 * 64;      // [128][64]; reused as att partial buffers
    float* sWg = sm + 2 * 128 * 64;  // [64][32]

    int tid = threadIdx.x;
    int node0 = blockIdx.x * 64;

    // stage weights
    for (int i = tid; i < 2048; i += 128) {       // 128*64/4 float4s
        int k = i >> 4, q = i & 15;
        const float* sp = (k < 64) ? (W_l + k * 64 + q * 4)
                                   : (W_r + (k - 64) * 64 + q * 4);
        *reinterpret_cast<float4*>(&sW[k * 64 + q * 4]) =
            *reinterpret_cast<const float4*>(sp);
    }
    for (int i = tid; i < 512; i += 128) {        // 64*32/4
        int k = i >> 3, q = i & 7;
        *reinterpret_cast<float4*>(&sWg[k * 32 + q * 4]) =
            *reinterpret_cast<const float4*>(W_g + k * 32 + q * 4);
    }
    // stage inputs transposed: sIn[k][node], k<64 = agg, k>=64 = x
    for (int i = tid; i < 1024; i += 128) {
        int node = i & 63, q = i >> 6;            // q 0..15
        int gnode = node0 + node;
        float4 va = make_float4(0.f, 0.f, 0.f, 0.f);
        float4 vx = make_float4(0.f, 0.f, 0.f, 0.f);
        if (gnode < n) {
            va = *reinterpret_cast<const float4*>(g_agg + (size_t)gnode * IN_C + q * 4);
            vx = *reinterpret_cast<const float4*>(x + (size_t)gnode * IN_C + q * 4);
        }
        int kb = q * 4;
        sIn[(kb + 0) * 64 + node] = va.x;
        sIn[(kb + 1) * 64 + node] = va.y;
        sIn[(kb + 2) * 64 + node] = va.z;
        sIn[(kb + 3) * 64 + node] = va.w;
        sIn[(kb + 64) * 64 + node] = vx.x;
        sIn[(kb + 65) * 64 + node] = vx.y;
        sIn[(kb + 66) * 64 + node] = vx.z;
        sIn[(kb + 67) * 64 + node] = vx.w;
    }
    __syncthreads();

    int ng = tid & 7;        // node group
    int cg = tid >> 3;       // col group (0..15)
    int ngb = ng * 8;
    int cb = cg * 4;

    unsigned long long acc[4][4];
#pragma unroll
    for (int j = 0; j < 4; j++)
#pragma unroll
        for (int p = 0; p < 4; p++) acc[j][p] = 0ull;

#pragma unroll 2
    for (int k = 0; k < 128; k++) {
        ulonglong2 inA = *reinterpret_cast<const ulonglong2*>(&sIn[k * 64 + ngb]);
        ulonglong2 inB = *reinterpret_cast<const ulonglong2*>(&sIn[k * 64 + ngb + 4]);
        float4 w = *reinterpret_cast<const float4*>(&sW[k * 64 + cb]);
        unsigned long long w0 = pack2(w.x), w1 = pack2(w.y);
        unsigned long long w2 = pack2(w.z), w3 = pack2(w.w);
        fma2(acc[0][0], inA.x, w0); fma2(acc[0][1], inA.y, w0);
        fma2(acc[0][2], inB.x, w0); fma2(acc[0][3], inB.y, w0);
        fma2(acc[1][0], inA.x, w1); fma2(acc[1][1], inA.y, w1);
        fma2(acc[1][2], inB.x, w1); fma2(acc[1][3], inB.y, w1);
        fma2(acc[2][0], inA.x, w2); fma2(acc[2][1], inA.y, w2);
        fma2(acc[2][2], inB.x, w2); fma2(acc[2][3], inB.y, w2);
        fma2(acc[3][0], inA.x, w3); fma2(acc[3][1], inA.y, w3);
        fma2(acc[3][2], inB.x, w3); fma2(acc[3][3], inB.y, w3);
    }
    __syncthreads();   // done with sIn/sW

    // h = relu(acc + b1) -> sH[c][node] (reuses sIn)
    float* sH = sIn;
    float b1v0 = b1[cb], b1v1 = b1[cb + 1], b1v2 = b1[cb + 2], b1v3 = b1[cb + 3];
#pragma unroll
    for (int p = 0; p < 4; p++) {
        float2 v0 = unpack2(acc[0][p]);
        float2 v1 = unpack2(acc[1][p]);
        float2 v2 = unpack2(acc[2][p]);
        float2 v3 = unpack2(acc[3][p]);
        int nb_ = ngb + 2 * p;
        *reinterpret_cast<unsigned long long*>(&sH[(cb + 0) * 64 + nb_]) =
            packf(fmaxf(v0.x + b1v0, 0.f), fmaxf(v0.y + b1v0, 0.f));
        *reinterpret_cast<unsigned long long*>(&sH[(cb + 1) * 64 + nb_]) =
            packf(fmaxf(v1.x + b1v1, 0.f), fmaxf(v1.y + b1v1, 0.f));
        *reinterpret_cast<unsigned long long*>(&sH[(cb + 2) * 64 + nb_]) =
            packf(fmaxf(v2.x + b1v2, 0.f), fmaxf(v2.y + b1v2, 0.f));
        *reinterpret_cast<unsigned long long*>(&sH[(cb + 3) * 64 + nb_]) =
            packf(fmaxf(v3.x + b1v3, 0.f), fmaxf(v3.y + b1v3, 0.f));
    }
    __syncthreads();

    // z = h @ Wg: each thread 8 nodes x 2 cols (c2 = cg*2)
    int c2 = cg * 2;
    unsigned long long z0[4], z1[4];
#pragma unroll
    for (int p = 0; p < 4; p++) { z0[p] = 0ull; z1[p] = 0ull; }

#pragma unroll 2
    for (int k = 0; k < 64; k++) {
        ulonglong2 inA = *reinterpret_cast<const ulonglong2*>(&sH[k * 64 + ngb]);
        ulonglong2 inB = *reinterpret_cast<const ulonglong2*>(&sH[k * 64 + ngb + 4]);
        float2 w = *reinterpret_cast<const float2*>(&sWg[k * 32 + c2]);
        unsigned long long w0 = pack2(w.x), w1 = pack2(w.y);
        fma2(z0[0], inA.x, w0); fma2(z0[1], inA.y, w0);
        fma2(z0[2], inB.x, w0); fma2(z0[3], inB.y, w0);
        fma2(z1[0], inA.x, w1); fma2(z1[1], inA.y, w1);
        fma2(z1[2], inB.x, w1); fma2(z1[3], inB.y, w1);
    }

    float asc0 = att_src[c2], asc1 = att_src[c2 + 1];
    float adc0 = att_dst[c2], adc1 = att_dst[c2 + 1];
    float* sAsP = sW;             // [16][64] (reuses sW)
    float* sAdP = sW + 16 * 64;

#pragma unroll
    for (int p = 0; p < 4; p++) {
        float2 za = unpack2(z0[p]);   // col c2,   nodes ngb+2p, ngb+2p+1
        float2 zb = unpack2(z1[p]);   // col c2+1
        int nA = ngb + 2 * p;
        int gA = node0 + nA;
        if (gA < n)
            *reinterpret_cast<float2*>(g_z + (size_t)gA * OUT_C + c2) =
                make_float2(za.x, zb.x);
        if (gA + 1 < n)
            *reinterpret_cast<float2*>(g_z + (size_t)(gA + 1) * OUT_C + c2) =
                make_float2(za.y, zb.y);
        sAsP[cg * 64 + nA]     = za.x * asc0 + zb.x * asc1;
        sAsP[cg * 64 + nA + 1] = za.y * asc0 + zb.y * asc1;
        sAdP[cg * 64 + nA]     = za.x * adc0 + zb.x * adc1;
        sAdP[cg * 64 + nA + 1] = za.y * adc0 + zb.y * adc1;
    }
    __syncthreads();

    if (tid < 64) {
        int g = node0 + tid;
        if (g < n) {
            float sa = 0.f, sd = 0.f;
#pragma unroll
            for (int c = 0; c < 16; c++) {
                sa += sAsP[c * 64 + tid];
                sd += sAdP[c * 64 + tid];
            }
            g_as[g] = sa;
            g_ad[g] = sd;
        }
    }
}

// ---------------- K5: fused GAT (vectorized gather) ----------------
__global__ void k_gat(const float* __restrict__ b2,
                      float* __restrict__ out,
                      int n) {
    int node = (blockIdx.x * blockDim.x + threadIdx.x) >> 5;
    int lane = threadIdx.x & 31;
    if (node >= n) return;
    int beg = g_off[node];
    int end = g_off[node + 1];
    int grp = lane >> 3;
    int q = lane & 7;

    float ad_ = g_ad[node];
    float e_self = lrelu(g_as[node] + ad_);

    float m = e_self;
    for (int j = beg + lane; j < end; j += 32)
        m = fmaxf(m, lrelu(g_as[g_adj[j]] + ad_));
#pragma unroll
    for (int o = 16; o > 0; o >>= 1)
        m = fmaxf(m, __shfl_xor_sync(FULL, m, o));

    float sum = 0.0f;
    float4 acc = make_float4(0.f, 0.f, 0.f, 0.f);
    if (grp == 0) {
        float w = __expf(e_self - m);
        sum = w;
        float4 zv = *reinterpret_cast<const float4*>(g_z + (size_t)node * OUT_C + q * 4);
        acc = make_float4(w * zv.x, w * zv.y, w * zv.z, w * zv.w);
    }
    for (int j = beg + grp; j < end; j += 4) {
        int s = g_adj[j];
        float w = __expf(lrelu(g_as[s] + ad_) - m);
        sum += w;
        float4 zv = *reinterpret_cast<const float4*>(g_z + (size_t)s * OUT_C + q * 4);
        acc.x = fmaf(w, zv.x, acc.x);
        acc.y = fmaf(w, zv.y, acc.y);
        acc.z = fmaf(w, zv.z, acc.z);
        acc.w = fmaf(w, zv.w, acc.w);
    }
    sum += __shfl_xor_sync(FULL, sum, 8);
    sum += __shfl_xor_sync(FULL, sum, 16);
    acc.x += __shfl_xor_sync(FULL, acc.x, 8);  acc.x += __shfl_xor_sync(FULL, acc.x, 16);
    acc.y += __shfl_xor_sync(FULL, acc.y, 8);  acc.y += __shfl_xor_sync(FULL, acc.y, 16);
    acc.z += __shfl_xor_sync(FULL, acc.z, 8);  acc.z += __shfl_xor_sync(FULL, acc.z, 16);
    acc.w += __shfl_xor_sync(FULL, acc.w, 8);  acc.w += __shfl_xor_sync(FULL, acc.w, 16);

    float inv = 1.0f / sum;
    float4 o4;
    o4.x = acc.x * inv + b2[q * 4 + 0];
    o4.y = acc.y * inv + b2[q * 4 + 1];
    o4.z = acc.z * inv + b2[q * 4 + 2];
    o4.w = acc.w * inv + b2[q * 4 + 3];

    float mx = fmaxf(fmaxf(o4.x, o4.y), fmaxf(o4.z, o4.w));
#pragma unroll
    for (int off = 1; off < 8; off <<= 1)
        mx = fmaxf(mx, __shfl_xor_sync(FULL, mx, off));
    float se = __expf(o4.x - mx) + __expf(o4.y - mx) + __expf(o4.z - mx) + __expf(o4.w - mx);
#pragma unroll
    for (int off = 1; off < 8; off <<= 1)
        se += __shfl_xor_sync(FULL, se, off);
    float ls = mx + logf(se);

    if (lane < 8) {
        float4 r = make_float4(o4.x - ls, o4.y - ls, o4.z - ls, o4.w - ls);
        *reinterpret_cast<float4*>(out + (size_t)node * OUT_C + q * 4) = r;
    }
}

// ---------------- launch ----------------
extern "C" void kernel_launch(void* const* d_in, const int* in_sizes, int n_in,
                              void* d_out, int out_size) {
    const float* x       = (const float*)d_in[0];
    const int*   ei      = (const int*)d_in[1];
    const float* W_l     = (const float*)d_in[2];
    const float* W_r     = (const float*)d_in[3];
    const float* b1      = (const float*)d_in[4];
    const float* W_g     = (const float*)d_in[5];
    const float* att_src = (const float*)d_in[6];
    const float* att_dst = (const float*)d_in[7];
    const float* b2      = (const float*)d_in[8];
    float* out = (float*)d_out;

    int N = in_sizes[0] / IN_C;
    int E = in_sizes[1] / 2;
    const int* src = ei;
    const int* dst = ei + E;

    void *p_cnt, *p_cur;
    cudaGetSymbolAddress(&p_cnt, g_cnt);
    cudaGetSymbolAddress(&p_cur, g_cur);
    cudaMemsetAsync(p_cnt, 0, (size_t)N * sizeof(int), 0);
    cudaMemsetAsync(p_cur, 0, (size_t)N * sizeof(int), 0);

    int nb_scan = (N + 1023) / 1024;
    k_hist<<<((unsigned)E + 255u) / 256u, 256>>>(dst, E);
    k_scan_local<<<nb_scan, 1024>>>(N);
    k_scan_bsums<<<1, 128>>>(nb_scan, N);
    k_scan_add<<<nb_scan, 1024>>>(N);
    k_fill<<<((unsigned)E + 255u) / 256u, 256>>>(src, dst, E);

    k_agg<<<(N + 7) / 8, 256>>>(x, N);

    size_t smemF = (size_t)(128 * 64 + 128 * 64 + 64 * 32) * sizeof(float);
    cudaFuncSetAttribute(k_forward, cudaFuncAttributeMaxDynamicSharedMemorySize,
                         (int)smemF);
    k_forward<<<(N + 63) / 64, 128, smemF>>>(x, W_l, W_r, b1, W_g,
                                             att_src, att_dst, N);

    k_gat<<<(N + 7) / 8, 256>>>(b2, out, N);
}